// round 2
// baseline (speedup 1.0000x reference)
#include <cuda_runtime.h>
#include <cuda_bf16.h>
#include <math.h>

// Problem dims
#define NB   256      // batch (sentences)
#define LT   128      // tokens per sentence
#define DI   300      // embedding dim
#define EE   512      // LSTM hidden
#define G4   2048     // 4*E
#define FF   4096     // 2*E*HOP
#define HOPS 4
#define NLAB 7
#define NLTOT (NB*LT) // 32768

// ---------------- device scratch ----------------
__device__ float g_emb[(size_t)NLTOT * DI];        // 39 MB
__device__ float g_xg [(size_t)NLTOT * 4096];      // 537 MB : [n*128+l][dir*2048 + gate*512 + e]
__device__ float g_enc[(size_t)NLTOT * 1024];      // 134 MB : [n*128+l][dir*512 + e]
__device__ float g_gbuf[(size_t)2 * NB * G4];      // 4 MB
__device__ float g_h[2 * NB * EE];
__device__ float g_c[2 * NB * EE];
__device__ float g_Mh[HOPS * 1024];
__device__ float g_s0[HOPS];
__device__ float g_attw[(size_t)NLTOT * HOPS];
__device__ float g_sent[(size_t)NB * FF];          // [n][e*4+h]
__device__ float g_sxg [(size_t)NB * 4096];        // [n][dir*2048 + gate*512 + e]
__device__ float g_sh[2 * 2 * EE];                 // [parity][dir][e]
__device__ float g_sout[(size_t)NB * 1024];        // [n][dir*512+e]
__device__ float g_bias_tok[4096];
__device__ float g_bias_sent[4096];
__device__ unsigned g_bar_cnt[2];
__device__ unsigned g_bar_flag[2];

__device__ __forceinline__ float sigf(float x) { return 1.f / (1.f + __expf(-x)); }

// ---------------- generic SGEMM body: C = A @ B^T (+bias[n]) (+add[m,n]) ----------------
#define BM 128
#define BN 64
#define BK 16

__device__ __forceinline__ void gemm_body(
    const float* __restrict__ A, int lda,
    const float* __restrict__ B, int ldb,
    const float* __restrict__ bias,
    const float* __restrict__ add, size_t ldadd,
    float* __restrict__ C, int ldc,
    int K, int m0, int n0,
    float As[][BM + 4], float Bs[][BN + 4])
{
    int tid = threadIdx.x;                 // 256 threads
    int arow = tid >> 2;                   // 0..63
    int acg  = (tid & 3) << 2;             // 0,4,8,12
    int ty = tid >> 4;                     // 0..15 (M)
    int tx = tid & 15;                     // 0..15 (N)

    float acc[8][4];
#pragma unroll
    for (int i = 0; i < 8; i++)
#pragma unroll
        for (int j = 0; j < 4; j++) acc[i][j] = 0.f;

    for (int k0 = 0; k0 < K; k0 += BK) {
        // load A tile 128x16 (two 64-row passes)
#pragma unroll
        for (int h = 0; h < 2; h++) {
            int r = arow + (h << 6);
            const float* ap = A + (size_t)(m0 + r) * lda + k0 + acg;
            float4 v;
            if (k0 + acg + 4 <= K) v = *(const float4*)ap;
            else {
                v.x = (k0 + acg + 0 < K) ? ap[0] : 0.f;
                v.y = (k0 + acg + 1 < K) ? ap[1] : 0.f;
                v.z = (k0 + acg + 2 < K) ? ap[2] : 0.f;
                v.w = (k0 + acg + 3 < K) ? ap[3] : 0.f;
            }
            As[acg + 0][r] = v.x; As[acg + 1][r] = v.y;
            As[acg + 2][r] = v.z; As[acg + 3][r] = v.w;
        }
        // load B tile 64x16
        {
            const float* bp = B + (size_t)(n0 + arow) * ldb + k0 + acg;
            float4 v;
            if (k0 + acg + 4 <= K) v = *(const float4*)bp;
            else {
                v.x = (k0 + acg + 0 < K) ? bp[0] : 0.f;
                v.y = (k0 + acg + 1 < K) ? bp[1] : 0.f;
                v.z = (k0 + acg + 2 < K) ? bp[2] : 0.f;
                v.w = (k0 + acg + 3 < K) ? bp[3] : 0.f;
            }
            Bs[acg + 0][arow] = v.x; Bs[acg + 1][arow] = v.y;
            Bs[acg + 2][arow] = v.z; Bs[acg + 3][arow] = v.w;
        }
        __syncthreads();
#pragma unroll
        for (int k = 0; k < BK; k++) {
            float4 a0 = *(const float4*)&As[k][ty << 3];
            float4 a1 = *(const float4*)&As[k][(ty << 3) + 4];
            float4 bb = *(const float4*)&Bs[k][tx << 2];
            float av[8] = {a0.x, a0.y, a0.z, a0.w, a1.x, a1.y, a1.z, a1.w};
            float bv[4] = {bb.x, bb.y, bb.z, bb.w};
#pragma unroll
            for (int i = 0; i < 8; i++)
#pragma unroll
                for (int j = 0; j < 4; j++) acc[i][j] += av[i] * bv[j];
        }
        __syncthreads();
    }
#pragma unroll
    for (int i = 0; i < 8; i++) {
        int m = m0 + (ty << 3) + i;
#pragma unroll
        for (int j = 0; j < 4; j++) {
            int n = n0 + (tx << 2) + j;
            float v = acc[i][j];
            if (bias) v += bias[n];
            if (add)  v += add[(size_t)m * ldadd + n];
            C[(size_t)m * ldc + n] = v;
        }
    }
}

// dual-direction GEMM: z selects B0/B1, bias block, C column block of 2048
__global__ void gemm2_kernel(const float* __restrict__ A, int lda,
                             const float* __restrict__ B0, const float* __restrict__ B1,
                             int ldb, const float* __restrict__ bias4096,
                             float* __restrict__ C, int ldc, int K)
{
    __shared__ float As[BK][BM + 4];
    __shared__ float Bs[BK][BN + 4];
    int dir = blockIdx.z;
    const float* B = dir ? B1 : B0;
    const float* bias = bias4096 ? (bias4096 + dir * 2048) : nullptr;
    gemm_body(A, lda, B, ldb, bias, nullptr, 0,
              C + dir * 2048, ldc, K, blockIdx.y * BM, blockIdx.x * BN, As, Bs);
}

// per-timestep recurrent GEMM: gbuf[dir] = h[dir] @ Whh_dir^T + xg[:, l_dir, dir-block]
__global__ void lstm_step_gemm_kernel(const float* __restrict__ whh_f,
                                      const float* __restrict__ whh_b, int t)
{
    __shared__ float As[BK][BM + 4];
    __shared__ float Bs[BK][BN + 4];
    int dir = blockIdx.z;
    const float* A = g_h + dir * (NB * EE);
    const float* B = dir ? whh_b : whh_f;
    int l = dir ? (LT - 1 - t) : t;
    const float* add = g_xg + (size_t)l * 4096 + dir * 2048;
    float* C = g_gbuf + (size_t)dir * NB * G4;
    gemm_body(A, EE, B, EE, nullptr, add, (size_t)LT * 4096,
              C, G4, EE, blockIdx.y * BM, blockIdx.x * BN, As, Bs);
}

__global__ void gate_kernel(int t)
{
    int idx = blockIdx.x * 256 + threadIdx.x;   // < 2*256*512
    int dir = idx >> 17;
    int rem = idx & 131071;
    int n = rem >> 9;
    int e = rem & 511;
    const float* gb = g_gbuf + (size_t)dir * NB * G4 + (size_t)n * G4;
    float gi = gb[e], gf = gb[512 + e], gg = gb[1024 + e], go = gb[1536 + e];
    float c = g_c[idx];
    c = sigf(gf) * c + sigf(gi) * tanhf(gg);
    float h = sigf(go) * tanhf(c);
    g_c[idx] = c;
    g_h[idx] = h;
    int l = dir ? (LT - 1 - t) : t;
    g_enc[(size_t)(n * LT + l) * 1024 + (dir << 9) + e] = h;
}

// ---------------- misc kernels ----------------
__global__ void init_kernel()
{
    int i = blockIdx.x * 256 + threadIdx.x;
    if (i < 2 * NB * EE) { g_h[i] = 0.f; g_c[i] = 0.f; }
    if (i < 2 * 2 * EE) g_sh[i] = 0.f;
    if (i < 2) { g_bar_cnt[i] = 0u; g_bar_flag[i] = 0u; }
}

__global__ void embed_kernel(const int* __restrict__ tokens,
                             const float* __restrict__ emb)
{
    size_t idx = (size_t)blockIdx.x * 256 + threadIdx.x;
    if (idx >= (size_t)NLTOT * DI) return;
    int nl = (int)(idx / DI);
    int d = (int)(idx - (size_t)nl * DI);
    g_emb[idx] = emb[(size_t)tokens[nl] * DI + d];
}

__global__ void bias_kernel(const float* b0, const float* b1, const float* b2, const float* b3,
                            const float* s0, const float* s1, const float* s2, const float* s3)
{
    int i = blockIdx.x * 256 + threadIdx.x;
    if (i < 2048) {
        g_bias_tok[i] = b0[i] + b1[i];
        g_bias_sent[i] = s0[i] + s1[i];
    } else if (i < 4096) {
        int j = i - 2048;
        g_bias_tok[i] = b2[j] + b3[j];
        g_bias_sent[i] = s2[j] + s3[j];
    }
}

// M[h,e] = sum_a ctx[h,a]*W[a,e];  s0[h] = ctx[h,:]·b   (folds attention to 4x1024)
__global__ void attnM_kernel(const float* __restrict__ W, const float* __restrict__ b,
                             const float* __restrict__ ctx)
{
    int i = blockIdx.x * 256 + threadIdx.x;
    if (i < HOPS * 1024) {
        int h = i >> 10, e = i & 1023;
        float s = 0.f;
        for (int a = 0; a < 256; a++) s += ctx[h * 256 + a] * W[a * 1024 + e];
        g_Mh[i] = s;
    }
    if (i < HOPS) {
        float s = 0.f;
        for (int a = 0; a < 256; a++) s += ctx[i * 256 + a] * b[a];
        g_s0[i] = s;
    }
}

// per (n,l): scores -> softmax over hops -> mask -> attw
__global__ void scores_kernel(const int* __restrict__ lengths)
{
    __shared__ float Msh[4096];
    __shared__ float s0s[4];
    int tid = threadIdx.x;
    for (int i = tid; i < 4096; i += 256) Msh[i] = g_Mh[i];
    if (tid < 4) s0s[tid] = g_s0[tid];
    __syncthreads();
    int gid = blockIdx.x * 8 + (tid >> 5);
    int lane = tid & 31;
    int n = gid >> 7, l = gid & 127;
    const float* row = g_enc + (size_t)gid * 1024;
    float a0 = 0, a1 = 0, a2 = 0, a3 = 0;
    for (int e = lane; e < 1024; e += 32) {
        float v = row[e];
        a0 += v * Msh[e];        a1 += v * Msh[1024 + e];
        a2 += v * Msh[2048 + e]; a3 += v * Msh[3072 + e];
    }
#pragma unroll
    for (int o = 16; o > 0; o >>= 1) {
        a0 += __shfl_xor_sync(0xffffffffu, a0, o);
        a1 += __shfl_xor_sync(0xffffffffu, a1, o);
        a2 += __shfl_xor_sync(0xffffffffu, a2, o);
        a3 += __shfl_xor_sync(0xffffffffu, a3, o);
    }
    if (lane == 0) {
        a0 += s0s[0]; a1 += s0s[1]; a2 += s0s[2]; a3 += s0s[3];
        float mx = fmaxf(fmaxf(a0, a1), fmaxf(a2, a3));
        float e0 = __expf(a0 - mx), e1 = __expf(a1 - mx);
        float e2 = __expf(a2 - mx), e3 = __expf(a3 - mx);
        float inv = 1.f / (e0 + e1 + e2 + e3);
        float msk = (l < lengths[n]) ? 1.f : 0.f;
        float4 w = make_float4(e0 * inv * msk, e1 * inv * msk, e2 * inv * msk, e3 * inv * msk);
        *(float4*)&g_attw[(size_t)gid * 4] = w;
    }
}

// sent[n][e*4+h] = sum_l enc[n,l,e]*attw[n,l,h]
__global__ void sent_accum_kernel()
{
    int n = blockIdx.x, tid = threadIdx.x;
    float acc[4][4];
#pragma unroll
    for (int j = 0; j < 4; j++)
#pragma unroll
        for (int h = 0; h < 4; h++) acc[j][h] = 0.f;
    const float* encn = g_enc + (size_t)n * LT * 1024;
    const float* wv = g_attw + (size_t)n * LT * 4;
    for (int l = 0; l < LT; l++) {
        float4 w = *(const float4*)&wv[l * 4];
        const float* row = encn + (size_t)l * 1024;
#pragma unroll
        for (int j = 0; j < 4; j++) {
            float v = row[tid + j * 256];
            acc[j][0] += v * w.x; acc[j][1] += v * w.y;
            acc[j][2] += v * w.z; acc[j][3] += v * w.w;
        }
    }
#pragma unroll
    for (int j = 0; j < 4; j++) {
        int e = tid + j * 256;
#pragma unroll
        for (int h = 0; h < 4; h++)
            g_sent[(size_t)n * FF + e * 4 + h] = acc[j][h];
    }
}

// ---------------- persistent sentence BiLSTM scan ----------------
// 64 blocks (32 per dir), 256 threads, weights for this block's 16 e-values in smem.
#define SENT_NB_PER_DIR 32
#define SENT_SMEM ((16 * 4 * 512 + 512) * 4)

__global__ void sent_scan_kernel(const float* __restrict__ whh_f,
                                 const float* __restrict__ whh_b)
{
    extern __shared__ float sm[];
    float* ws = sm;                 // 16 e * 4 gates * 512 k
    float* hs = sm + 16 * 4 * 512;  // 512
    int dir = blockIdx.x >> 5;
    int bslot = blockIdx.x & 31;
    int e_base = bslot * 16;
    const float* whh = dir ? whh_b : whh_f;
    int tid = threadIdx.x;

    for (int idx = tid * 4; idx < 32768; idx += 256 * 4) {
        int gate = idx >> 13;
        int rem = idx & 8191;
        int el = rem >> 9;
        int k = rem & 511;
        *(float4*)&ws[idx] =
            *(const float4*)&whh[(size_t)((gate << 9) + e_base + el) * 512 + k];
    }
    int warp = tid >> 5, lane = tid & 31;
    int group = lane >> 3, lane8 = lane & 7;
    float creg[2] = {0.f, 0.f};
    __syncthreads();

    for (int s = 0; s < 256; s++) {
        int rd = s & 1;
        for (int i = tid; i < 512; i += 256)
            hs[i] = __ldcg(&g_sh[(rd * 2 + dir) * 512 + i]);
        __syncthreads();
        int nt = dir ? (255 - s) : s;
        const float* xrow = g_sxg + (size_t)nt * 4096 + (dir << 11);
#pragma unroll
        for (int i = 0; i < 2; i++) {
            int el = (warp << 1) + i;
            int e = e_base + el;
            const float4* w4 = (const float4*)&ws[((group << 4) + el) << 9];
            const float4* h4 = (const float4*)hs;
            float acc = 0.f;
#pragma unroll
            for (int m = 0; m < 16; m++) {
                float4 a = w4[lane8 + (m << 3)];
                float4 b = h4[lane8 + (m << 3)];
                acc += a.x * b.x + a.y * b.y + a.z * b.z + a.w * b.w;
            }
            acc += __shfl_xor_sync(0xffffffffu, acc, 1);
            acc += __shfl_xor_sync(0xffffffffu, acc, 2);
            acc += __shfl_xor_sync(0xffffffffu, acc, 4);
            float g = acc + xrow[(group << 9) + e];
            float gi = __shfl_sync(0xffffffffu, g, 0);
            float gf = __shfl_sync(0xffffffffu, g, 8);
            float gg = __shfl_sync(0xffffffffu, g, 16);
            float go = __shfl_sync(0xffffffffu, g, 24);
            if (lane == 0) {
                float c = creg[i];
                c = sigf(gf) * c + sigf(gi) * tanhf(gg);
                float h = sigf(go) * tanhf(c);
                creg[i] = c;
                int wr = rd ^ 1;
                g_sh[(wr * 2 + dir) * 512 + e] = h;
                g_sout[(size_t)nt * 1024 + (dir << 9) + e] = h;
            }
        }
        __syncthreads();
        if (tid == 0) {
            __threadfence();
            unsigned v = atomicAdd(&g_bar_cnt[dir], 1u);
            if (v == (unsigned)(SENT_NB_PER_DIR - 1)) {
                g_bar_cnt[dir] = 0u;
                __threadfence();
                atomicExch(&g_bar_flag[dir], (unsigned)(s + 1));
            } else {
                while (atomicAdd(&g_bar_flag[dir], 0u) < (unsigned)(s + 1)) { }
            }
        }
        __syncthreads();
    }
}

__global__ void final_kernel(const float* __restrict__ lw,
                             const float* __restrict__ lb,
                             float* __restrict__ out)
{
    int n = blockIdx.x, lane = threadIdx.x;
    const float* s = g_sout + (size_t)n * 1024;
    for (int c = 0; c < NLAB; c++) {
        float a = 0.f;
        for (int e = lane; e < 1024; e += 32) a += s[e] * lw[c * 1024 + e];
#pragma unroll
        for (int o = 16; o > 0; o >>= 1) a += __shfl_xor_sync(0xffffffffu, a, o);
        if (lane == 0) out[n * NLAB + c] = a + lb[c];
    }
}

// ---------------- launch ----------------
extern "C" void kernel_launch(void* const* d_in, const int* in_sizes, int n_in,
                              void* d_out, int out_size)
{
    const int*   tokens     = (const int*)d_in[0];
    const int*   lengths    = (const int*)d_in[1];
    const float* embedding  = (const float*)d_in[2];
    const float* tok_Wih_f  = (const float*)d_in[3];
    const float* tok_Whh_f  = (const float*)d_in[4];
    const float* tok_bih_f  = (const float*)d_in[5];
    const float* tok_bhh_f  = (const float*)d_in[6];
    const float* tok_Wih_b  = (const float*)d_in[7];
    const float* tok_Whh_b  = (const float*)d_in[8];
    const float* tok_bih_b  = (const float*)d_in[9];
    const float* tok_bhh_b  = (const float*)d_in[10];
    const float* attn_W     = (const float*)d_in[11];
    const float* attn_b     = (const float*)d_in[12];
    const float* attn_ctx   = (const float*)d_in[13];
    const float* sent_Wih_f = (const float*)d_in[14];
    const float* sent_Whh_f = (const float*)d_in[15];
    const float* sent_bih_f = (const float*)d_in[16];
    const float* sent_bhh_f = (const float*)d_in[17];
    const float* sent_Wih_b = (const float*)d_in[18];
    const float* sent_Whh_b = (const float*)d_in[19];
    const float* sent_bih_b = (const float*)d_in[20];
    const float* sent_bhh_b = (const float*)d_in[21];
    const float* lin_W      = (const float*)d_in[22];
    const float* lin_b      = (const float*)d_in[23];
    float* out = (float*)d_out;

    float *p_emb, *p_xg, *p_sent, *p_sxg, *p_btok, *p_bsent;
    cudaGetSymbolAddress((void**)&p_emb, g_emb);
    cudaGetSymbolAddress((void**)&p_xg, g_xg);
    cudaGetSymbolAddress((void**)&p_sent, g_sent);
    cudaGetSymbolAddress((void**)&p_sxg, g_sxg);
    cudaGetSymbolAddress((void**)&p_btok, g_bias_tok);
    cudaGetSymbolAddress((void**)&p_bsent, g_bias_sent);

    cudaFuncSetAttribute(sent_scan_kernel,
                         cudaFuncAttributeMaxDynamicSharedMemorySize, SENT_SMEM);

    init_kernel<<<2057, 256>>>();
    embed_kernel<<<(int)(((size_t)NLTOT * DI + 255) / 256), 256>>>(tokens, embedding);
    bias_kernel<<<16, 256>>>(tok_bih_f, tok_bhh_f, tok_bih_b, tok_bhh_b,
                             sent_bih_f, sent_bhh_f, sent_bih_b, sent_bhh_b);
    attnM_kernel<<<16, 256>>>(attn_W, attn_b, attn_ctx);

    // xg = emb @ [Wih_f;Wih_b]^T + biases   (M=32768, N=2048/dir, K=300)
    gemm2_kernel<<<dim3(32, 256, 2), 256>>>(p_emb, DI, tok_Wih_f, tok_Wih_b, DI,
                                            p_btok, p_xg, 4096, DI);

    // token BiLSTM scan: 128 steps x (recurrent GEMM + gates)
    for (int t = 0; t < LT; t++) {
        lstm_step_gemm_kernel<<<dim3(32, 2, 2), 256>>>(tok_Whh_f, tok_Whh_b, t);
        gate_kernel<<<1024, 256>>>(t);
    }

    // attention (folded) + sentence feature
    scores_kernel<<<4096, 256>>>(lengths);
    sent_accum_kernel<<<256, 256>>>();

    // sentence input projection (M=256, N=2048/dir, K=4096)
    gemm2_kernel<<<dim3(32, 2, 2), 256>>>(p_sent, FF, sent_Wih_f, sent_Wih_b, FF,
                                          p_bsent, p_sxg, 4096, FF);

    // persistent sentence BiLSTM
    sent_scan_kernel<<<64, 256, SENT_SMEM>>>(sent_Whh_f, sent_Whh_b);

    final_kernel<<<256, 32>>>(lin_W, lin_b, out);
}

// round 3
// speedup vs baseline: 1.5665x; 1.5665x over previous
#include <cuda_runtime.h>
#include <cuda_bf16.h>
#include <math.h>

// Problem dims
#define NB   256      // batch (sentences)
#define LT   128      // tokens per sentence
#define DI   300      // embedding dim
#define EE   512      // LSTM hidden
#define G4   2048     // 4*E
#define FF   4096     // 2*E*HOP
#define HOPS 4
#define NLAB 7
#define NLTOT (NB*LT) // 32768

// ---------------- device scratch ----------------
__device__ float g_emb[(size_t)NLTOT * DI];        // 39 MB
__device__ float g_xg [(size_t)NLTOT * 4096];      // 537 MB : [n*128+l][dir*2048 + gate*512 + e]
__device__ float g_enc[(size_t)NLTOT * 1024];      // 134 MB : [n*128+l][dir*512 + e]
__device__ float g_gbuf[(size_t)2 * NB * G4];      // 4 MB
__device__ float g_h[2 * NB * EE];
__device__ float g_c[2 * NB * EE];
__device__ float g_Mh[HOPS * 1024];
__device__ float g_s0[HOPS];
__device__ float g_attw[(size_t)NLTOT * HOPS];
__device__ float g_sent[(size_t)NB * FF];          // [n][e*4+h]
__device__ float g_sxg [(size_t)NB * 4096];        // [n][dir*2048 + gate*512 + e]
__device__ float g_sh[2 * 2 * EE];                 // [parity][dir][e]
__device__ float g_sout[(size_t)NB * 1024];        // [n][dir*512+e]
__device__ float g_bias_tok[4096];
__device__ float g_bias_sent[4096];
__device__ unsigned g_bar_cnt[2];
__device__ unsigned g_bar_flag[2];

__device__ __forceinline__ float sigf(float x) { return 1.f / (1.f + __expf(-x)); }

__device__ __forceinline__ unsigned f2tf32(float x)
{
    unsigned u;
    asm("cvt.rna.tf32.f32 %0, %1;" : "=r"(u) : "f"(x));
    return u;
}

__device__ __forceinline__ void mma8(float* c, const unsigned* a, const unsigned* b)
{
    asm volatile(
        "mma.sync.aligned.m16n8k8.row.col.f32.tf32.tf32.f32 "
        "{%0,%1,%2,%3},{%4,%5,%6,%7},{%8,%9},{%0,%1,%2,%3};"
        : "+f"(c[0]), "+f"(c[1]), "+f"(c[2]), "+f"(c[3])
        : "r"(a[0]), "r"(a[1]), "r"(a[2]), "r"(a[3]), "r"(b[0]), "r"(b[1]));
}

// ---------------- tf32 tensor-core SGEMM body: C = A @ B^T (+bias[n]) (+add[m,n]) ----------------
#define BM 128
#define BN 64
#define BK 16
#define AST 20   // As row stride (floats) — (20*qr+qc) mod 32 all-distinct => conflict-free frags
#define BST 20

__device__ __forceinline__ void gemm_tf32_body(
    const float* __restrict__ A, int lda,
    const float* __restrict__ B, int ldb,
    const float* __restrict__ bias,
    const float* __restrict__ add, size_t ldadd,
    float* __restrict__ C, int ldc,
    int K, int m0, int n0,
    float* As, float* Bs)
{
    int tid = threadIdx.x;                 // 256 threads
    int warp = tid >> 5, lane = tid & 31;
    int wm = warp & 3;                     // 0..3 -> m offset wm*32
    int wn = warp >> 2;                    // 0..1 -> n offset wn*32
    int qr = lane >> 2;                    // 0..7
    int qc = lane & 3;                     // 0..3

    int lr = tid >> 2;                     // 0..63 (loader row)
    int lc = (tid & 3) << 2;               // 0,4,8,12 (loader k)

    float acc[2][4][4];
#pragma unroll
    for (int mf = 0; mf < 2; mf++)
#pragma unroll
        for (int nf = 0; nf < 4; nf++)
#pragma unroll
            for (int r = 0; r < 4; r++) acc[mf][nf][r] = 0.f;

    for (int k0 = 0; k0 < K; k0 += BK) {
        // load A tile 128x16 (two 64-row passes), convert to tf32 bit patterns
#pragma unroll
        for (int h = 0; h < 2; h++) {
            int r = lr + (h << 6);
            const float* ap = A + (size_t)(m0 + r) * lda + k0 + lc;
            float4 v;
            if (k0 + lc + 4 <= K) v = *(const float4*)ap;
            else {
                v.x = (k0 + lc + 0 < K) ? ap[0] : 0.f;
                v.y = (k0 + lc + 1 < K) ? ap[1] : 0.f;
                v.z = (k0 + lc + 2 < K) ? ap[2] : 0.f;
                v.w = (k0 + lc + 3 < K) ? ap[3] : 0.f;
            }
            v.x = __uint_as_float(f2tf32(v.x));
            v.y = __uint_as_float(f2tf32(v.y));
            v.z = __uint_as_float(f2tf32(v.z));
            v.w = __uint_as_float(f2tf32(v.w));
            *(float4*)&As[r * AST + lc] = v;
        }
        // load B tile 64x16
        {
            const float* bp = B + (size_t)(n0 + lr) * ldb + k0 + lc;
            float4 v;
            if (k0 + lc + 4 <= K) v = *(const float4*)bp;
            else {
                v.x = (k0 + lc + 0 < K) ? bp[0] : 0.f;
                v.y = (k0 + lc + 1 < K) ? bp[1] : 0.f;
                v.z = (k0 + lc + 2 < K) ? bp[2] : 0.f;
                v.w = (k0 + lc + 3 < K) ? bp[3] : 0.f;
            }
            v.x = __uint_as_float(f2tf32(v.x));
            v.y = __uint_as_float(f2tf32(v.y));
            v.z = __uint_as_float(f2tf32(v.z));
            v.w = __uint_as_float(f2tf32(v.w));
            *(float4*)&Bs[lr * BST + lc] = v;
        }
        __syncthreads();
#pragma unroll
        for (int kk = 0; kk < BK; kk += 8) {
            unsigned af[2][4], bf[4][2];
#pragma unroll
            for (int mf = 0; mf < 2; mf++) {
                int mb = (wm << 5) + (mf << 4);
                af[mf][0] = __float_as_uint(As[(mb + qr) * AST + kk + qc]);
                af[mf][1] = __float_as_uint(As[(mb + qr + 8) * AST + kk + qc]);
                af[mf][2] = __float_as_uint(As[(mb + qr) * AST + kk + qc + 4]);
                af[mf][3] = __float_as_uint(As[(mb + qr + 8) * AST + kk + qc + 4]);
            }
#pragma unroll
            for (int nf = 0; nf < 4; nf++) {
                int nb = (wn << 5) + (nf << 3);
                bf[nf][0] = __float_as_uint(Bs[(nb + qr) * BST + kk + qc]);
                bf[nf][1] = __float_as_uint(Bs[(nb + qr) * BST + kk + qc + 4]);
            }
#pragma unroll
            for (int mf = 0; mf < 2; mf++)
#pragma unroll
                for (int nf = 0; nf < 4; nf++)
                    mma8(acc[mf][nf], af[mf], bf[nf]);
        }
        __syncthreads();
    }

    // epilogue: c0,c1 -> row qr, cols 2qc,2qc+1; c2,c3 -> row qr+8
#pragma unroll
    for (int mf = 0; mf < 2; mf++) {
#pragma unroll
        for (int nf = 0; nf < 4; nf++) {
            int n = n0 + (wn << 5) + (nf << 3) + (qc << 1);
#pragma unroll
            for (int rh = 0; rh < 2; rh++) {
                int m = m0 + (wm << 5) + (mf << 4) + qr + (rh << 3);
                float2 v;
                v.x = acc[mf][nf][rh * 2 + 0];
                v.y = acc[mf][nf][rh * 2 + 1];
                if (bias) { v.x += bias[n]; v.y += bias[n + 1]; }
                if (add) {
                    v.x += add[(size_t)m * ldadd + n];
                    v.y += add[(size_t)m * ldadd + n + 1];
                }
                *(float2*)&C[(size_t)m * ldc + n] = v;
            }
        }
    }
}

// dual-direction GEMM: z selects B0/B1, bias block, C column block of 2048
__global__ void gemm2_kernel(const float* __restrict__ A, int lda,
                             const float* __restrict__ B0, const float* __restrict__ B1,
                             int ldb, const float* __restrict__ bias4096,
                             float* __restrict__ C, int ldc, int K)
{
    __shared__ float As[BM * AST];
    __shared__ float Bs[BN * BST];
    int dir = blockIdx.z;
    const float* B = dir ? B1 : B0;
    const float* bias = bias4096 ? (bias4096 + dir * 2048) : nullptr;
    gemm_tf32_body(A, lda, B, ldb, bias, nullptr, 0,
                   C + dir * 2048, ldc, K, blockIdx.y * BM, blockIdx.x * BN, As, Bs);
}

// per-timestep recurrent GEMM: gbuf[dir] = h[dir] @ Whh_dir^T + xg[:, l_dir, dir-block]
__global__ void lstm_step_gemm_kernel(const float* __restrict__ whh_f,
                                      const float* __restrict__ whh_b, int t)
{
    __shared__ float As[BM * AST];
    __shared__ float Bs[BN * BST];
    int dir = blockIdx.z;
    const float* A = g_h + dir * (NB * EE);
    const float* B = dir ? whh_b : whh_f;
    int l = dir ? (LT - 1 - t) : t;
    const float* add = g_xg + (size_t)l * 4096 + dir * 2048;
    float* C = g_gbuf + (size_t)dir * NB * G4;
    gemm_tf32_body(A, EE, B, EE, nullptr, add, (size_t)LT * 4096,
                   C, G4, EE, blockIdx.y * BM, blockIdx.x * BN, As, Bs);
}

__global__ void gate_kernel(int t)
{
    int idx = blockIdx.x * 256 + threadIdx.x;   // < 2*256*512
    int dir = idx >> 17;
    int rem = idx & 131071;
    int n = rem >> 9;
    int e = rem & 511;
    const float* gb = g_gbuf + (size_t)dir * NB * G4 + (size_t)n * G4;
    float gi = gb[e], gf = gb[512 + e], gg = gb[1024 + e], go = gb[1536 + e];
    float c = g_c[idx];
    c = sigf(gf) * c + sigf(gi) * tanhf(gg);
    float h = sigf(go) * tanhf(c);
    g_c[idx] = c;
    g_h[idx] = h;
    int l = dir ? (LT - 1 - t) : t;
    g_enc[(size_t)(n * LT + l) * 1024 + (dir << 9) + e] = h;
}

// ---------------- misc kernels ----------------
__global__ void init_kernel()
{
    int i = blockIdx.x * 256 + threadIdx.x;
    if (i < 2 * NB * EE) { g_h[i] = 0.f; g_c[i] = 0.f; }
    if (i < 2 * 2 * EE) g_sh[i] = 0.f;
    if (i < 2) { g_bar_cnt[i] = 0u; g_bar_flag[i] = 0u; }
}

__global__ void embed_kernel(const int* __restrict__ tokens,
                             const float* __restrict__ emb)
{
    size_t idx = (size_t)blockIdx.x * 256 + threadIdx.x;
    if (idx >= (size_t)NLTOT * DI) return;
    int nl = (int)(idx / DI);
    int d = (int)(idx - (size_t)nl * DI);
    g_emb[idx] = emb[(size_t)tokens[nl] * DI + d];
}

__global__ void bias_kernel(const float* b0, const float* b1, const float* b2, const float* b3,
                            const float* s0, const float* s1, const float* s2, const float* s3)
{
    int i = blockIdx.x * 256 + threadIdx.x;
    if (i < 2048) {
        g_bias_tok[i] = b0[i] + b1[i];
        g_bias_sent[i] = s0[i] + s1[i];
    } else if (i < 4096) {
        int j = i - 2048;
        g_bias_tok[i] = b2[j] + b3[j];
        g_bias_sent[i] = s2[j] + s3[j];
    }
}

// M[h,e] = sum_a ctx[h,a]*W[a,e];  s0[h] = ctx[h,:]·b   (folds attention to 4x1024)
__global__ void attnM_kernel(const float* __restrict__ W, const float* __restrict__ b,
                             const float* __restrict__ ctx)
{
    int i = blockIdx.x * 256 + threadIdx.x;
    if (i < HOPS * 1024) {
        int h = i >> 10, e = i & 1023;
        float s = 0.f;
        for (int a = 0; a < 256; a++) s += ctx[h * 256 + a] * W[a * 1024 + e];
        g_Mh[i] = s;
    }
    if (i < HOPS) {
        float s = 0.f;
        for (int a = 0; a < 256; a++) s += ctx[i * 256 + a] * b[a];
        g_s0[i] = s;
    }
}

// per (n,l): scores -> softmax over hops -> mask -> attw
__global__ void scores_kernel(const int* __restrict__ lengths)
{
    __shared__ float Msh[4096];
    __shared__ float s0s[4];
    int tid = threadIdx.x;
    for (int i = tid; i < 4096; i += 256) Msh[i] = g_Mh[i];
    if (tid < 4) s0s[tid] = g_s0[tid];
    __syncthreads();
    int gid = blockIdx.x * 8 + (tid >> 5);
    int lane = tid & 31;
    int n = gid >> 7, l = gid & 127;
    const float* row = g_enc + (size_t)gid * 1024;
    float a0 = 0, a1 = 0, a2 = 0, a3 = 0;
    for (int e = lane; e < 1024; e += 32) {
        float v = row[e];
        a0 += v * Msh[e];        a1 += v * Msh[1024 + e];
        a2 += v * Msh[2048 + e]; a3 += v * Msh[3072 + e];
    }
#pragma unroll
    for (int o = 16; o > 0; o >>= 1) {
        a0 += __shfl_xor_sync(0xffffffffu, a0, o);
        a1 += __shfl_xor_sync(0xffffffffu, a1, o);
        a2 += __shfl_xor_sync(0xffffffffu, a2, o);
        a3 += __shfl_xor_sync(0xffffffffu, a3, o);
    }
    if (lane == 0) {
        a0 += s0s[0]; a1 += s0s[1]; a2 += s0s[2]; a3 += s0s[3];
        float mx = fmaxf(fmaxf(a0, a1), fmaxf(a2, a3));
        float e0 = __expf(a0 - mx), e1 = __expf(a1 - mx);
        float e2 = __expf(a2 - mx), e3 = __expf(a3 - mx);
        float inv = 1.f / (e0 + e1 + e2 + e3);
        float msk = (l < lengths[n]) ? 1.f : 0.f;
        float4 w = make_float4(e0 * inv * msk, e1 * inv * msk, e2 * inv * msk, e3 * inv * msk);
        *(float4*)&g_attw[(size_t)gid * 4] = w;
    }
}

// sent[n][e*4+h] = sum_l enc[n,l,e]*attw[n,l,h]
__global__ void sent_accum_kernel()
{
    int n = blockIdx.x, tid = threadIdx.x;
    float acc[4][4];
#pragma unroll
    for (int j = 0; j < 4; j++)
#pragma unroll
        for (int h = 0; h < 4; h++) acc[j][h] = 0.f;
    const float* encn = g_enc + (size_t)n * LT * 1024;
    const float* wv = g_attw + (size_t)n * LT * 4;
    for (int l = 0; l < LT; l++) {
        float4 w = *(const float4*)&wv[l * 4];
        const float* row = encn + (size_t)l * 1024;
#pragma unroll
        for (int j = 0; j < 4; j++) {
            float v = row[tid + j * 256];
            acc[j][0] += v * w.x; acc[j][1] += v * w.y;
            acc[j][2] += v * w.z; acc[j][3] += v * w.w;
        }
    }
#pragma unroll
    for (int j = 0; j < 4; j++) {
        int e = tid + j * 256;
#pragma unroll
        for (int h = 0; h < 4; h++)
            g_sent[(size_t)n * FF + e * 4 + h] = acc[j][h];
    }
}

// ---------------- persistent sentence BiLSTM scan ----------------
// 64 blocks (32 per dir), 256 threads, weights for this block's 16 e-values in smem.
#define SENT_NB_PER_DIR 32
#define SENT_SMEM ((16 * 4 * 512 + 512) * 4)

__global__ void sent_scan_kernel(const float* __restrict__ whh_f,
                                 const float* __restrict__ whh_b)
{
    extern __shared__ float sm[];
    float* ws = sm;                 // 16 e * 4 gates * 512 k
    float* hs = sm + 16 * 4 * 512;  // 512
    int dir = blockIdx.x >> 5;
    int bslot = blockIdx.x & 31;
    int e_base = bslot * 16;
    const float* whh = dir ? whh_b : whh_f;
    int tid = threadIdx.x;

    for (int idx = tid * 4; idx < 32768; idx += 256 * 4) {
        int gate = idx >> 13;
        int rem = idx & 8191;
        int el = rem >> 9;
        int k = rem & 511;
        *(float4*)&ws[idx] =
            *(const float4*)&whh[(size_t)((gate << 9) + e_base + el) * 512 + k];
    }
    int warp = tid >> 5, lane = tid & 31;
    int group = lane >> 3, lane8 = lane & 7;
    float creg[2] = {0.f, 0.f};
    __syncthreads();

    for (int s = 0; s < 256; s++) {
        int rd = s & 1;
        for (int i = tid; i < 512; i += 256)
            hs[i] = __ldcg(&g_sh[(rd * 2 + dir) * 512 + i]);
        __syncthreads();
        int nt = dir ? (255 - s) : s;
        const float* xrow = g_sxg + (size_t)nt * 4096 + (dir << 11);
#pragma unroll
        for (int i = 0; i < 2; i++) {
            int el = (warp << 1) + i;
            int e = e_base + el;
            const float4* w4 = (const float4*)&ws[((group << 4) + el) << 9];
            const float4* h4 = (const float4*)hs;
            float acc = 0.f;
#pragma unroll
            for (int m = 0; m < 16; m++) {
                float4 a = w4[lane8 + (m << 3)];
                float4 b = h4[lane8 + (m << 3)];
                acc += a.x * b.x + a.y * b.y + a.z * b.z + a.w * b.w;
            }
            acc += __shfl_xor_sync(0xffffffffu, acc, 1);
            acc += __shfl_xor_sync(0xffffffffu, acc, 2);
            acc += __shfl_xor_sync(0xffffffffu, acc, 4);
            float g = acc + xrow[(group << 9) + e];
            float gi = __shfl_sync(0xffffffffu, g, 0);
            float gf = __shfl_sync(0xffffffffu, g, 8);
            float gg = __shfl_sync(0xffffffffu, g, 16);
            float go = __shfl_sync(0xffffffffu, g, 24);
            if (lane == 0) {
                float c = creg[i];
                c = sigf(gf) * c + sigf(gi) * tanhf(gg);
                float h = sigf(go) * tanhf(c);
                creg[i] = c;
                int wr = rd ^ 1;
                g_sh[(wr * 2 + dir) * 512 + e] = h;
                g_sout[(size_t)nt * 1024 + (dir << 9) + e] = h;
            }
        }
        __syncthreads();
        if (tid == 0) {
            __threadfence();
            unsigned v = atomicAdd(&g_bar_cnt[dir], 1u);
            if (v == (unsigned)(SENT_NB_PER_DIR - 1)) {
                g_bar_cnt[dir] = 0u;
                __threadfence();
                atomicExch(&g_bar_flag[dir], (unsigned)(s + 1));
            } else {
                while (atomicAdd(&g_bar_flag[dir], 0u) < (unsigned)(s + 1)) { }
            }
        }
        __syncthreads();
    }
}

__global__ void final_kernel(const float* __restrict__ lw,
                             const float* __restrict__ lb,
                             float* __restrict__ out)
{
    int n = blockIdx.x, lane = threadIdx.x;
    const float* s = g_sout + (size_t)n * 1024;
    for (int c = 0; c < NLAB; c++) {
        float a = 0.f;
        for (int e = lane; e < 1024; e += 32) a += s[e] * lw[c * 1024 + e];
#pragma unroll
        for (int o = 16; o > 0; o >>= 1) a += __shfl_xor_sync(0xffffffffu, a, o);
        if (lane == 0) out[n * NLAB + c] = a + lb[c];
    }
}

// ---------------- launch ----------------
extern "C" void kernel_launch(void* const* d_in, const int* in_sizes, int n_in,
                              void* d_out, int out_size)
{
    const int*   tokens     = (const int*)d_in[0];
    const int*   lengths    = (const int*)d_in[1];
    const float* embedding  = (const float*)d_in[2];
    const float* tok_Wih_f  = (const float*)d_in[3];
    const float* tok_Whh_f  = (const float*)d_in[4];
    const float* tok_bih_f  = (const float*)d_in[5];
    const float* tok_bhh_f  = (const float*)d_in[6];
    const float* tok_Wih_b  = (const float*)d_in[7];
    const float* tok_Whh_b  = (const float*)d_in[8];
    const float* tok_bih_b  = (const float*)d_in[9];
    const float* tok_bhh_b  = (const float*)d_in[10];
    const float* attn_W     = (const float*)d_in[11];
    const float* attn_b     = (const float*)d_in[12];
    const float* attn_ctx   = (const float*)d_in[13];
    const float* sent_Wih_f = (const float*)d_in[14];
    const float* sent_Whh_f = (const float*)d_in[15];
    const float* sent_bih_f = (const float*)d_in[16];
    const float* sent_bhh_f = (const float*)d_in[17];
    const float* sent_Wih_b = (const float*)d_in[18];
    const float* sent_Whh_b = (const float*)d_in[19];
    const float* sent_bih_b = (const float*)d_in[20];
    const float* sent_bhh_b = (const float*)d_in[21];
    const float* lin_W      = (const float*)d_in[22];
    const float* lin_b      = (const float*)d_in[23];
    float* out = (float*)d_out;

    float *p_emb, *p_xg, *p_sent, *p_sxg, *p_btok, *p_bsent;
    cudaGetSymbolAddress((void**)&p_emb, g_emb);
    cudaGetSymbolAddress((void**)&p_xg, g_xg);
    cudaGetSymbolAddress((void**)&p_sent, g_sent);
    cudaGetSymbolAddress((void**)&p_sxg, g_sxg);
    cudaGetSymbolAddress((void**)&p_btok, g_bias_tok);
    cudaGetSymbolAddress((void**)&p_bsent, g_bias_sent);

    cudaFuncSetAttribute(sent_scan_kernel,
                         cudaFuncAttributeMaxDynamicSharedMemorySize, SENT_SMEM);

    init_kernel<<<2057, 256>>>();
    embed_kernel<<<(int)(((size_t)NLTOT * DI + 255) / 256), 256>>>(tokens, embedding);
    bias_kernel<<<16, 256>>>(tok_bih_f, tok_bhh_f, tok_bih_b, tok_bhh_b,
                             sent_bih_f, sent_bhh_f, sent_bih_b, sent_bhh_b);
    attnM_kernel<<<16, 256>>>(attn_W, attn_b, attn_ctx);

    // xg = emb @ [Wih_f;Wih_b]^T + biases   (M=32768, N=2048/dir, K=300)
    gemm2_kernel<<<dim3(32, 256, 2), 256>>>(p_emb, DI, tok_Wih_f, tok_Wih_b, DI,
                                            p_btok, p_xg, 4096, DI);

    // token BiLSTM scan: 128 steps x (recurrent GEMM + gates)
    for (int t = 0; t < LT; t++) {
        lstm_step_gemm_kernel<<<dim3(32, 2, 2), 256>>>(tok_Whh_f, tok_Whh_b, t);
        gate_kernel<<<1024, 256>>>(t);
    }

    // attention (folded) + sentence feature
    scores_kernel<<<4096, 256>>>(lengths);
    sent_accum_kernel<<<256, 256>>>();

    // sentence input projection (M=256, N=2048/dir, K=4096)
    gemm2_kernel<<<dim3(32, 2, 2), 256>>>(p_sent, FF, sent_Wih_f, sent_Wih_b, FF,
                                          p_bsent, p_sxg, 4096, FF);

    // persistent sentence BiLSTM
    sent_scan_kernel<<<64, 256, SENT_SMEM>>>(sent_Whh_f, sent_Whh_b);

    final_kernel<<<256, 32>>>(lin_W, lin_b, out);
}